// round 16
// baseline (speedup 1.0000x reference)
#include <cuda_runtime.h>
#include <cuda_fp16.h>

#define H_DIM 512
#define W_DIM 512
#define RPB   16      // output rows per block -> 1024 blocks = single wave
#define NTHREADS 128  // 4 px/thread * 128 threads = 512 columns = full row
#define MAX_BLOCKS 8192

__device__ float    g_part[MAX_BLOCKS];
__device__ unsigned g_ticket;   // zero-init; restored to 0 by last block each run

// Raw per-row data: float4 + ONE predicated edge scalar (only lanes 0 and 31
// load it; other lanes get halo values via SHFL at consume time).
struct RawV { float4 v; float e; };

__device__ __forceinline__ RawV ldrowv(const float* __restrict__ row,
                                       int x0, int eoff, bool edge) {
    RawV r;
    r.v = *reinterpret_cast<const float4*>(row + x0);
    // e is consumed only on lanes 0/31 where it IS loaded (clamped address
    // covers both image borders and warp seams).
    if (edge) r.e = __ldg(row + eoff);
    return r;
}

// Per-row Sobel pieces in half2, pixel pairs (01) and (23):
//   d = val(x-1) - val(x+1) ; s = val(x-1) + 2 val(x) + val(x+1)
struct HS { __half2 d01, d23, s01, s23; };

// Build HS from raw row: halo from neighbor lanes via SHFL (data is one
// iteration old -> SHFL latency off the load critical path), edge lanes
// use the predicated scalar.
__device__ __forceinline__ HS mk_hs(const RawV& a, int lane, __half2 two2) {
    float m_sh = __shfl_up_sync(0xffffffffu, a.v.w, 1);
    float p_sh = __shfl_down_sync(0xffffffffu, a.v.x, 1);
    float m = (lane == 0)  ? a.e : m_sh;
    float p = (lane == 31) ? a.e : p_sh;
    __half2 mx = __floats2half2_rn(m,     a.v.x);
    __half2 xy = __floats2half2_rn(a.v.x, a.v.y);
    __half2 yz = __floats2half2_rn(a.v.y, a.v.z);
    __half2 zw = __floats2half2_rn(a.v.z, a.v.w);
    __half2 wp = __floats2half2_rn(a.v.w, p);
    HS r;
    r.d01 = __hsub2(mx, yz);                       // (m-y, x-z)
    r.d23 = __hsub2(yz, wp);                       // (y-w, z-p)
    r.s01 = __hadd2(__hfma2(two2, xy, mx), yz);    // (m+2x+y, x+2y+z)
    r.s23 = __hadd2(__hfma2(two2, zw, yz), wp);    // (y+2z+w, z+2w+p)
    return r;
}

// Packed normal for a pixel pair, fully in half2:
//   q = gx^2+gy^2 ; length^2 = 0.0625 + 3.9375 q ; w = h2rsqrt(.) = 1/length
//   nx = gx*w, ny = gy*w, nz = (0.25 - 0.125 q)*w   (0.25 pre-folded)
__device__ __forceinline__ void nrm2(__half2 dP, __half2 dC, __half2 dN,
                                     __half2 sP, __half2 sN,
                                     __half2 two2, __half2 cq, __half2 c3,
                                     __half2 c0, __half2 cb,
                                     __half2& nx, __half2& ny, __half2& nz) {
    __half2 gx = __hadd2(__hfma2(two2, dC, dP), dN);
    __half2 gy = __hsub2(sP, sN);
    __half2 q  = __hfma2(gx, gx, __hmul2(gy, gy));
    __half2 w2 = h2rsqrt(__hfma2(c3, q, c0));
    __half2 su = __hfma2(cb, q, cq);               // 0.25 - q/8
    nx = __hmul2(gx, w2);
    ny = __hmul2(gy, w2);
    nz = __hmul2(su, w2);
}

__global__ void __launch_bounds__(NTHREADS, 8)
heightmap_loss_kernel(const float* __restrict__ gen, const float* __restrict__ tgt,
                      float* __restrict__ out, double inv_n) {
    const int b    = blockIdx.y;
    const int y0   = blockIdx.x * RPB;
    const int lane = threadIdx.x & 31;
    const int x0   = threadIdx.x * 4;
    const int xm   = max(x0 - 1, 0);
    const int xp   = min(x0 + 4, W_DIM - 1);
    const int eoff = (lane == 0) ? xm : xp;        // edge-lane scalar address
    const bool edge = (lane == 0) || (lane == 31);
    const int nblocks = gridDim.x * gridDim.y;
    const int bid     = blockIdx.y * gridDim.x + blockIdx.x;

    const __half2 two2 = __float2half2_rn(2.f);
    const __half2 cq   = __float2half2_rn(0.25f);
    const __half2 c3   = __float2half2_rn(3.9375f);
    const __half2 c0   = __float2half2_rn(0.0625f);
    const __half2 cb   = __float2half2_rn(-0.125f);

    const float* __restrict__ gimg = gen + (size_t)b * (H_DIM * W_DIM);
    const float* __restrict__ timg = tgt + (size_t)b * (H_DIM * W_DIM);

    // rolling 3-row half2 window + 1-row raw prefetch buffer per image
    HS gP, gC, tP, tC;
    RawV gR, tR;     // raw data for the row that becomes N next iteration
    {
        int ym = max(y0 - 1, 0);
        gP = mk_hs(ldrowv(gimg + ym * W_DIM, x0, eoff, edge), lane, two2);
        tP = mk_hs(ldrowv(timg + ym * W_DIM, x0, eoff, edge), lane, two2);
        gC = mk_hs(ldrowv(gimg + y0 * W_DIM, x0, eoff, edge), lane, two2);
        tC = mk_hs(ldrowv(timg + y0 * W_DIM, x0, eoff, edge), lane, two2);
        gR = ldrowv(gimg + (y0 + 1) * W_DIM, x0, eoff, edge);  // y0+1 <= 497
        tR = ldrowv(timg + (y0 + 1) * W_DIM, x0, eoff, edge);
    }

    // merged packed accumulators (A: px01, B: px23)
    __half2 accA = __float2half2_rn(0.f), accB = accA;

    #pragma unroll
    for (int yy = 0; yy < RPB; yy++) {
        // Prefetch raw row yy+2 FIRST — consumers are a full iteration away.
        int yn2 = min(y0 + yy + 2, H_DIM - 1);
        RawV gR2 = ldrowv(gimg + yn2 * W_DIM, x0, eoff, edge);
        RawV tR2 = ldrowv(timg + yn2 * W_DIM, x0, eoff, edge);

        // N row from raw data loaded LAST iteration (already arrived).
        HS gN = mk_hs(gR, lane, two2);
        HS tN = mk_hs(tR, lane, two2);

        __half2 gnx, gny, gnz, tnx, tny, tnz;
        // pair 01
        nrm2(gP.d01, gC.d01, gN.d01, gP.s01, gN.s01,
             two2, cq, c3, c0, cb, gnx, gny, gnz);
        nrm2(tP.d01, tC.d01, tN.d01, tP.s01, tN.s01,
             two2, cq, c3, c0, cb, tnx, tny, tnz);
        accA = __hadd2(accA,
               __hadd2(__hadd2(__habs2(__hsub2(gnx, tnx)),
                               __habs2(__hsub2(gny, tny))),
                       __habs2(__hsub2(gnz, tnz))));
        // pair 23
        nrm2(gP.d23, gC.d23, gN.d23, gP.s23, gN.s23,
             two2, cq, c3, c0, cb, gnx, gny, gnz);
        nrm2(tP.d23, tC.d23, tN.d23, tP.s23, tN.s23,
             two2, cq, c3, c0, cb, tnx, tny, tnz);
        accB = __hadd2(accB,
               __hadd2(__hadd2(__habs2(__hsub2(gnx, tnx)),
                               __habs2(__hsub2(gny, tny))),
                       __habs2(__hsub2(gnz, tnz))));

        gP = gC; gC = gN; gR = gR2;
        tP = tC; tC = tN; tR = tR2;
    }

    float acc = __low2float(accA) + __high2float(accA)
              + __low2float(accB) + __high2float(accB);

    // warp reduce
    #pragma unroll
    for (int o = 16; o > 0; o >>= 1)
        acc += __shfl_down_sync(0xffffffffu, acc, o);

    __shared__ float ws[NTHREADS / 32];
    __shared__ bool  isLast;
    if (lane == 0) ws[threadIdx.x >> 5] = acc;
    __syncthreads();
    if (threadIdx.x == 0) {
        g_part[bid] = ws[0] + ws[1] + ws[2] + ws[3];
        __threadfence();
        unsigned prev = atomicAdd(&g_ticket, 1u);
        isLast = (prev == (unsigned)(nblocks - 1));
    }
    __syncthreads();

    // Last block to finish performs the deterministic final reduction.
    if (isLast) {
        double s = 0.0;
        for (int i = threadIdx.x; i < nblocks; i += NTHREADS)
            s += (double)g_part[i];
        #pragma unroll
        for (int o = 16; o > 0; o >>= 1)
            s += __shfl_down_sync(0xffffffffu, s, o);
        __shared__ double ds[NTHREADS / 32];
        if (lane == 0) ds[threadIdx.x >> 5] = s;
        __syncthreads();
        if (threadIdx.x == 0) {
            double t = ds[0] + ds[1] + ds[2] + ds[3];
            out[0] = (float)(t * inv_n);
            g_ticket = 0u;   // restore invariant for graph replay
        }
    }
}

extern "C" void kernel_launch(void* const* d_in, const int* in_sizes, int n_in,
                              void* d_out, int out_size) {
    const float* gen = (const float*)d_in[0];
    const float* tgt = (const float*)d_in[1];
    float* out = (float*)d_out;

    const int total = in_sizes[0];              // B*1*H*W
    const int B = total / (H_DIM * W_DIM);

    dim3 grid(H_DIM / RPB, B);
    heightmap_loss_kernel<<<grid, NTHREADS>>>(gen, tgt, out,
                                              1.0 / (3.0 * (double)total));
}